// round 13
// baseline (speedup 1.0000x reference)
#include <cuda_runtime.h>
#include <math.h>

#define IMG_W 128
#define IMG_H 128
#define MAX_N 4096
#define TILE_W 8
#define TILE_H 4
#define SEGS   16
#define SLOTS  8
#define NTILES ((IMG_W / TILE_W) * (IMG_H / TILE_H))   // 512

// Packed hot params, 2 x float4 per gaussian:
//  [0] u, v, ia, ibc
//  [1] idd, op, z, bbox packed as uchar4 (minu, maxu, minv, maxv)
__device__ float4 g_pk[MAX_N * 2];
// Colors (phase B only).
__device__ float4 g_col[MAX_N];
// Tightened cull box (refbox ∩ 3-sigma ellipse extents) - cull only.
__device__ float4 g_cbox[MAX_N];

__global__ __launch_bounds__(32)
void gs_precompute(const float* __restrict__ means,
                   const float* __restrict__ scales,
                   const float* __restrict__ rots,
                   const float* __restrict__ opac,
                   const float* __restrict__ feats,
                   const float* __restrict__ cam,
                   const float* __restrict__ focal_p,
                   const float* __restrict__ cx_p,
                   const float* __restrict__ cy_p,
                   int N)
{
    int g = blockIdx.x * blockDim.x + threadIdx.x;
    if (g >= N) return;

    const float f  = focal_p[0];
    const float cx = cx_p[0];
    const float cy = cy_p[0];

    float R[3][3], t[3];
    #pragma unroll
    for (int i = 0; i < 3; i++) {
        #pragma unroll
        for (int k = 0; k < 3; k++) R[i][k] = cam[i * 4 + k];
        t[i] = cam[i * 4 + 3];
    }

    float mean[3], sc[3];
    #pragma unroll
    for (int k = 0; k < 3; k++) {
        mean[k] = means[g * 3 + k];
        sc[k]   = __expf(scales[g * 3 + k]);
    }

    float qw = rots[g * 4 + 0], qx = rots[g * 4 + 1];
    float qy = rots[g * 4 + 2], qz = rots[g * 4 + 3];
    float two_s = __fdividef(2.0f, qw * qw + qx * qx + qy * qy + qz * qz);
    float xx = qx * qx * two_s, xy = qx * qy * two_s, xz = qx * qz * two_s;
    float yw = qy * qw * two_s, yy = qy * qy * two_s, yz = qy * qz * two_s;
    float zw = qz * qw * two_s, zz = qz * qz * two_s, xw = qx * qw * two_s;
    float M[3][3];
    M[0][0] = 1.0f - (yy + zz); M[0][1] = xy - zw;          M[0][2] = xz + yw;
    M[1][0] = xy + zw;          M[1][1] = 1.0f - (xx + zz); M[1][2] = yz - xw;
    M[2][0] = xz - yw;          M[2][1] = yz + xw;          M[2][2] = 1.0f - (xx + yy);

    float mc[3];
    #pragma unroll
    for (int i = 0; i < 3; i++)
        mc[i] = R[i][0] * mean[0] + R[i][1] * mean[1] + R[i][2] * mean[2] + t[i];
    float z = mc[2];
    float inv_z = __fdividef(1.0f, z);
    float u = mc[0] * inv_z * f + cx;
    float v = mc[1] * inv_z * f + cy;

    float J0[3], J1[3];
    #pragma unroll
    for (int k = 0; k < 3; k++) {
        J0[k] = f * R[0][k] - cx * R[2][k];
        J1[k] = f * R[1][k] - cy * R[2][k];
    }

    float V0[3], V1[3];
    #pragma unroll
    for (int k = 0; k < 3; k++) {
        V0[k] = (J0[0] * M[0][k] + J0[1] * M[1][k] + J0[2] * M[2][k]) * sc[k];
        V1[k] = (J1[0] * M[0][k] + J1[1] * M[1][k] + J1[2] * M[2][k]) * sc[k];
    }

    float inv_z2 = inv_z * inv_z;
    float a = (V0[0] * V0[0] + V0[1] * V0[1] + V0[2] * V0[2]) * inv_z2;
    float b = (V0[0] * V1[0] + V0[1] * V1[1] + V0[2] * V1[2]) * inv_z2;
    float d = (V1[0] * V1[0] + V1[1] * V1[1] + V1[2] * V1[2]) * inv_z2;
    float det = a * d - b * b;
    float invdet = __fdividef(1.0f, det);
    float ia  = d * invdet;
    float ibc = -(b + b) * invdet;
    float idd = a * invdet;

    float op = __fdividef(1.0f, 1.0f + __expf(-opac[g]));
    float c0 = __fdividef(1.0f, 1.0f + __expf(-feats[g * 3 + 0]));
    float c1 = __fdividef(1.0f, 1.0f + __expf(-feats[g * 3 + 1]));
    float c2 = __fdividef(1.0f, 1.0f + __expf(-feats[g * 3 + 2]));

    float smax = fmaxf(sc[0], fmaxf(sc[1], sc[2]));
    float radius = smax * f * inv_z * 3.0f;

    float minu = fmaxf(0.0f, truncf(u - radius));
    float maxu = truncf(u + radius);
    float minv = fmaxf(0.0f, truncf(v - radius));
    float maxv = truncf(v + radius);

    // pack bbox as bytes; clamps preserve exact comparisons for px,py in 0..127
    unsigned pumin = (unsigned)fminf(minu, 255.0f);
    unsigned pumax = (unsigned)fminf(fmaxf(maxu, 0.0f), 255.0f);
    unsigned pvmin = (unsigned)fminf(minv, 255.0f);
    unsigned pvmax = (unsigned)fminf(fmaxf(maxv, 0.0f), 255.0f);
    unsigned pack = pumin | (pumax << 8) | (pvmin << 16) | (pvmax << 24);

    g_pk[g * 2 + 0] = make_float4(u, v, ia, ibc);
    g_pk[g * 2 + 1] = make_float4(idd, op, z, __uint_as_float(pack));
    g_col[g] = make_float4(c0, c1, c2, 0.0f);

    // tightened cull box: mask requires in_refbox AND d2<9;
    // d2<9 implies |dx| <= 3*sqrt(cov_xx), |dy| <= 3*sqrt(cov_yy)
    float ru = 3.0f * sqrtf(fmaxf(a, 0.0f));
    float rv = 3.0f * sqrtf(fmaxf(d, 0.0f));
    g_cbox[g] = make_float4(fmaxf(minu, u - ru), fminf(maxu, u + ru),
                            fmaxf(minv, v - rv), fminf(maxv, v + rv));
}

// 16 warps / 8x4 tile, 4 blocks/SM (single wave). Phase A: per-warp segment
// cull + local strict-running-min records (z strictly decreasing within a
// segment). Phase B: thr = prefix-min of earlier segments' lastz; a record
// is globally accepted iff z < thr (suffix property). Per-warp Tseg ->
// prefix product -> T_in -> per-warp affine fold (A,B); warp 0 applies the
// 16 affine maps in order.
__global__ __launch_bounds__(SEGS * 32, 4)
void gs_render(float* __restrict__ out, int N)
{
    extern __shared__ char smem_raw[];
    float2*         s_rec   = (float2*)smem_raw;                    // 32 KB
    float4*         s_AB    = (float4*)(s_rec + SEGS * SLOTS * 32); //  8 KB
    float*          s_lastz = (float*)(s_AB + SEGS * 32);           //  2 KB
    float*          s_Tseg  = s_lastz + SEGS * 32;                  //  2 KB
    unsigned short* s_gid   = (unsigned short*)(s_Tseg + SEGS * 32);//  8 KB
    unsigned short* s_idx   = s_gid + SEGS * SLOTS * 32;            //  2 KB

    const int warp = threadIdx.x >> 5;
    const int lane = threadIdx.x & 31;

    const int segLen = (N + SEGS - 1) / SEGS;
    const int segBeg = warp * segLen;
    const int segEnd = min(segBeg + segLen, N);
    const float INF = __int_as_float(0x7f800000);

    const int tile = blockIdx.x;
    const int tx0 = (tile & 15) * TILE_W;
    const int ty0 = (tile >> 4) * TILE_H;
    const int px_i = tx0 + (lane & (TILE_W - 1));
    const int py_i = ty0 + (lane >> 3);
    const float px = (float)px_i;
    const float py = (float)py_i;
    const float ftx0 = (float)tx0, ftx1 = (float)(tx0 + TILE_W - 1);
    const float fty0 = (float)ty0, fty1 = (float)(ty0 + TILE_H - 1);

    // ---- cull segment against tightened box (order-preserving) ----
    unsigned short* myidx = s_idx + warp * segLen;
    int cnt = 0;
    for (int j = segBeg; j < segEnd; j += 32) {
        int g = j + lane;
        bool ok = false;
        if (g < segEnd) {
            float4 cb = __ldg(&g_cbox[g]);
            ok = (cb.x <= ftx1) & (cb.y >= ftx0) &
                 (cb.z <= fty1) & (cb.w >= fty0);
        }
        unsigned m = __ballot_sync(0xffffffffu, ok);
        if (ok) myidx[cnt + __popc(m & ((1u << lane) - 1u))] = (unsigned short)g;
        cnt += __popc(m);
    }

    // ---- phase A: local strict running minima -> smem records ----
    const int entBase = warp * SLOTS * 32 + lane;
    float runmin = INF;
    float lastz  = INF;
    int mycnt = 0;
    for (int i0 = 0; i0 < cnt; i0 += 2) {
        int r = cnt - i0;
        int gg[2]; float4 P1[2], P2[2];
        #pragma unroll
        for (int k = 0; k < 2; k++) {
            int idx = (k < r) ? (int)myidx[i0 + k] : 0;
            gg[k] = idx & (MAX_N - 1);
            P1[k] = __ldg(&g_pk[gg[k] * 2 + 0]);
            P2[k] = __ldg(&g_pk[gg[k] * 2 + 1]);
        }
        #pragma unroll
        for (int k = 0; k < 2; k++) {
            float dx = px - P1[k].x;
            float dy = py - P1[k].y;
            float d2 = P1[k].z * dx * dx + P1[k].w * dx * dy + P2[k].x * dy * dy;
            unsigned pk = __float_as_uint(P2[k].w);
            bool inb = (px_i >= (int)(pk & 0xFF)) &
                       (px_i <= (int)((pk >> 8) & 0xFF)) &
                       (py_i >= (int)((pk >> 16) & 0xFF)) &
                       (py_i <= (int)(pk >> 24));
            bool acc = (k < r) & inb & (d2 < 9.0f) & (P2[k].z < runmin);
            float a  = P2[k].y * __expf(-0.5f * d2);  // speculative, MUFU
            if (acc) {
                runmin = P2[k].z;
                if (mycnt < SLOTS) {
                    s_rec[entBase + mycnt * 32] = make_float2(P2[k].z, a);
                    s_gid[entBase + mycnt * 32] = (unsigned short)gg[k];
                    lastz = P2[k].z;
                }
                mycnt++;
            }
        }
    }
    const int c = min(mycnt, SLOTS);
    s_lastz[warp * 32 + lane] = lastz;
    __syncthreads();

    // ---- phase B1: thr (prefix-min of lastz) + local transmittance Tseg ----
    float thr = INF;
    #pragma unroll
    for (int s = 0; s < SEGS - 1; s++) {
        float v = s_lastz[s * 32 + lane];
        thr = (s < warp) ? fminf(thr, v) : thr;
    }

    float Tseg = 1.0f;
    for (int j = 0; j < c; j++) {
        float2 rec = s_rec[entBase + j * 32];
        Tseg *= (rec.x < thr) ? (1.0f - rec.y) : 1.0f;
    }
    s_Tseg[warp * 32 + lane] = Tseg;
    __syncthreads();

    // ---- phase B2: T_in prefix product + affine fold (A, B) ----
    float T_in = 1.0f;
    #pragma unroll
    for (int s = 0; s < SEGS - 1; s++) {
        float v = s_Tseg[s * 32 + lane];
        T_in *= (s < warp) ? v : 1.0f;
    }

    float A = 1.0f, B0 = 0.0f, B1 = 0.0f, B2 = 0.0f;
    {
        float T = T_in;
        for (int j = 0; j < c; j++) {
            float2 rec = s_rec[entBase + j * 32];
            int gid = (int)s_gid[entBase + j * 32] & (MAX_N - 1);
            float4 col = __ldg(&g_col[gid]);
            float na = (rec.x < thr) ? rec.y * T : 0.0f;
            float om = 1.0f - na;
            A  = A  * om;
            B0 = B0 * om + col.x * na;
            B1 = B1 * om + col.y * na;
            B2 = B2 * om + col.z * na;
            T  = T - na;                  // T' = T(1-a) = T - a*T
        }
    }
    s_AB[warp * 32 + lane] = make_float4(A, B0, B1, B2);
    __syncthreads();

    // ---- phase B3: apply 16 affine maps in order (warp 0) ----
    if (warp == 0) {
        float i0v = 0.0f, i1v = 0.0f, i2v = 0.0f;
        #pragma unroll
        for (int s = 0; s < SEGS; s++) {
            float4 ab = s_AB[s * 32 + lane];
            i0v = ab.x * i0v + ab.y;
            i1v = ab.x * i1v + ab.z;
            i2v = ab.x * i2v + ab.w;
        }
        int o = (py_i * IMG_W + px_i) * 3;
        out[o + 0] = i0v;
        out[o + 1] = i1v;
        out[o + 2] = i2v;
    }
}

extern "C" void kernel_launch(void* const* d_in, const int* in_sizes, int n_in,
                              void* d_out, int out_size)
{
    const float* means  = (const float*)d_in[0];
    const float* scales = (const float*)d_in[1];
    const float* rots   = (const float*)d_in[2];
    const float* opac   = (const float*)d_in[3];
    const float* feats  = (const float*)d_in[4];
    const float* cam    = (const float*)d_in[5];
    const float* focal  = (const float*)d_in[6];
    const float* cx     = (const float*)d_in[7];
    const float* cy     = (const float*)d_in[8];
    float* out = (float*)d_out;

    int N = in_sizes[0] / 3;
    if (N > MAX_N) N = MAX_N;

    // 32-thread blocks spread the latency-bound per-gaussian math across SMs
    gs_precompute<<<(N + 31) / 32, 32>>>(means, scales, rots, opac, feats,
                                         cam, focal, cx, cy, N);

    int segLen = (N + SEGS - 1) / SEGS;
    size_t smem = (size_t)SEGS * SLOTS * 32 * sizeof(float2)          // records
                + (size_t)SEGS * 32 * sizeof(float4)                  // A,B
                + (size_t)SEGS * 32 * sizeof(float) * 2               // lastz,Tseg
                + (size_t)SEGS * SLOTS * 32 * sizeof(unsigned short)  // gids
                + (size_t)SEGS * segLen * sizeof(unsigned short);     // idx lists
    cudaFuncSetAttribute(gs_render, cudaFuncAttributeMaxDynamicSharedMemorySize,
                         56 * 1024);

    dim3 block(SEGS * 32, 1);
    gs_render<<<NTILES, block, smem>>>(out, N);
}

// round 14
// speedup vs baseline: 1.1350x; 1.1350x over previous
#include <cuda_runtime.h>
#include <math.h>

#define IMG_W 128
#define IMG_H 128
#define MAX_N 4096
#define TILE_W 8
#define TILE_H 4
#define SEGS   16
#define SLOTS  8
#define NTILES ((IMG_W / TILE_W) * (IMG_H / TILE_H))   // 512

// Packed hot params, 2 x float4 per gaussian:
//  [0] u, v, ia, ibc
//  [1] idd, op, z, bbox packed as uchar4 (minu, maxu, minv, maxv)
__device__ float4 g_pk[MAX_N * 2];
// Colors (phase B only).
__device__ float4 g_col[MAX_N];
// Tightened cull box (refbox ∩ 3-sigma ellipse extents) - cull only.
__device__ float4 g_cbox[MAX_N];

__global__ __launch_bounds__(32)
void gs_precompute(const float* __restrict__ means,
                   const float* __restrict__ scales,
                   const float* __restrict__ rots,
                   const float* __restrict__ opac,
                   const float* __restrict__ feats,
                   const float* __restrict__ cam,
                   const float* __restrict__ focal_p,
                   const float* __restrict__ cx_p,
                   const float* __restrict__ cy_p,
                   int N)
{
    int g = blockIdx.x * blockDim.x + threadIdx.x;
    if (g >= N) return;

    const float f  = focal_p[0];
    const float cx = cx_p[0];
    const float cy = cy_p[0];

    float R[3][3], t[3];
    #pragma unroll
    for (int i = 0; i < 3; i++) {
        #pragma unroll
        for (int k = 0; k < 3; k++) R[i][k] = cam[i * 4 + k];
        t[i] = cam[i * 4 + 3];
    }

    float mean[3], sc[3];
    #pragma unroll
    for (int k = 0; k < 3; k++) {
        mean[k] = means[g * 3 + k];
        sc[k]   = __expf(scales[g * 3 + k]);
    }

    float qw = rots[g * 4 + 0], qx = rots[g * 4 + 1];
    float qy = rots[g * 4 + 2], qz = rots[g * 4 + 3];
    float two_s = __fdividef(2.0f, qw * qw + qx * qx + qy * qy + qz * qz);
    float xx = qx * qx * two_s, xy = qx * qy * two_s, xz = qx * qz * two_s;
    float yw = qy * qw * two_s, yy = qy * qy * two_s, yz = qy * qz * two_s;
    float zw = qz * qw * two_s, zz = qz * qz * two_s, xw = qx * qw * two_s;
    float M[3][3];
    M[0][0] = 1.0f - (yy + zz); M[0][1] = xy - zw;          M[0][2] = xz + yw;
    M[1][0] = xy + zw;          M[1][1] = 1.0f - (xx + zz); M[1][2] = yz - xw;
    M[2][0] = xz - yw;          M[2][1] = yz + xw;          M[2][2] = 1.0f - (xx + yy);

    float mc[3];
    #pragma unroll
    for (int i = 0; i < 3; i++)
        mc[i] = R[i][0] * mean[0] + R[i][1] * mean[1] + R[i][2] * mean[2] + t[i];
    float z = mc[2];
    float inv_z = __fdividef(1.0f, z);
    float u = mc[0] * inv_z * f + cx;
    float v = mc[1] * inv_z * f + cy;

    float J0[3], J1[3];
    #pragma unroll
    for (int k = 0; k < 3; k++) {
        J0[k] = f * R[0][k] - cx * R[2][k];
        J1[k] = f * R[1][k] - cy * R[2][k];
    }

    float V0[3], V1[3];
    #pragma unroll
    for (int k = 0; k < 3; k++) {
        V0[k] = (J0[0] * M[0][k] + J0[1] * M[1][k] + J0[2] * M[2][k]) * sc[k];
        V1[k] = (J1[0] * M[0][k] + J1[1] * M[1][k] + J1[2] * M[2][k]) * sc[k];
    }

    float inv_z2 = inv_z * inv_z;
    float a = (V0[0] * V0[0] + V0[1] * V0[1] + V0[2] * V0[2]) * inv_z2;
    float b = (V0[0] * V1[0] + V0[1] * V1[1] + V0[2] * V1[2]) * inv_z2;
    float d = (V1[0] * V1[0] + V1[1] * V1[1] + V1[2] * V1[2]) * inv_z2;
    float det = a * d - b * b;
    float invdet = __fdividef(1.0f, det);
    float ia  = d * invdet;
    float ibc = -(b + b) * invdet;
    float idd = a * invdet;

    float op = __fdividef(1.0f, 1.0f + __expf(-opac[g]));
    float c0 = __fdividef(1.0f, 1.0f + __expf(-feats[g * 3 + 0]));
    float c1 = __fdividef(1.0f, 1.0f + __expf(-feats[g * 3 + 1]));
    float c2 = __fdividef(1.0f, 1.0f + __expf(-feats[g * 3 + 2]));

    float smax = fmaxf(sc[0], fmaxf(sc[1], sc[2]));
    float radius = smax * f * inv_z * 3.0f;

    float minu = fmaxf(0.0f, truncf(u - radius));
    float maxu = truncf(u + radius);
    float minv = fmaxf(0.0f, truncf(v - radius));
    float maxv = truncf(v + radius);

    // pack bbox as bytes; clamps preserve exact comparisons for px,py in 0..127
    unsigned pumin = (unsigned)fminf(minu, 255.0f);
    unsigned pumax = (unsigned)fminf(fmaxf(maxu, 0.0f), 255.0f);
    unsigned pvmin = (unsigned)fminf(minv, 255.0f);
    unsigned pvmax = (unsigned)fminf(fmaxf(maxv, 0.0f), 255.0f);
    unsigned pack = pumin | (pumax << 8) | (pvmin << 16) | (pvmax << 24);

    g_pk[g * 2 + 0] = make_float4(u, v, ia, ibc);
    g_pk[g * 2 + 1] = make_float4(idd, op, z, __uint_as_float(pack));
    g_col[g] = make_float4(c0, c1, c2, 0.0f);

    // tightened cull box: mask requires in_refbox AND d2<9;
    // d2<9 implies |dx| <= 3*sqrt(cov_xx), |dy| <= 3*sqrt(cov_yy)
    float ru = 3.0f * sqrtf(fmaxf(a, 0.0f));
    float rv = 3.0f * sqrtf(fmaxf(d, 0.0f));
    g_cbox[g] = make_float4(fmaxf(minu, u - ru), fminf(maxu, u + ru),
                            fmaxf(minv, v - rv), fminf(maxv, v + rv));
}

// 16 warps / 8x4 tile, 3 blocks/SM (regs ~40, no spills). Phase A: per-warp
// segment cull + local strict-running-min records (z strictly decreasing
// within a segment). Phase B: thr = prefix-min of earlier segments' lastz;
// a record is globally accepted iff z < thr (suffix property). Per-warp
// Tseg -> prefix product -> T_in -> per-warp affine fold (A,B); warp 0
// applies the 16 affine maps in order.
__global__ __launch_bounds__(SEGS * 32, 3)
void gs_render(float* __restrict__ out, int N)
{
    extern __shared__ char smem_raw[];
    float2*         s_rec   = (float2*)smem_raw;                    // 32 KB
    float4*         s_AB    = (float4*)(s_rec + SEGS * SLOTS * 32); //  8 KB
    float*          s_lastz = (float*)(s_AB + SEGS * 32);           //  2 KB
    float*          s_Tseg  = s_lastz + SEGS * 32;                  //  2 KB
    unsigned short* s_gid   = (unsigned short*)(s_Tseg + SEGS * 32);//  8 KB
    unsigned short* s_idx   = s_gid + SEGS * SLOTS * 32;            //  2 KB

    const int warp = threadIdx.x >> 5;
    const int lane = threadIdx.x & 31;

    const int segLen = (N + SEGS - 1) / SEGS;
    const int segBeg = warp * segLen;
    const int segEnd = min(segBeg + segLen, N);
    const float INF = __int_as_float(0x7f800000);

    const int tile = blockIdx.x;
    const int tx0 = (tile & 15) * TILE_W;
    const int ty0 = (tile >> 4) * TILE_H;
    const int px_i = tx0 + (lane & (TILE_W - 1));
    const int py_i = ty0 + (lane >> 3);
    const float px = (float)px_i;
    const float py = (float)py_i;
    const float ftx0 = (float)tx0, ftx1 = (float)(tx0 + TILE_W - 1);
    const float fty0 = (float)ty0, fty1 = (float)(ty0 + TILE_H - 1);

    // ---- cull segment against tightened box (order-preserving) ----
    unsigned short* myidx = s_idx + warp * segLen;
    int cnt = 0;
    for (int j = segBeg; j < segEnd; j += 32) {
        int g = j + lane;
        bool ok = false;
        if (g < segEnd) {
            float4 cb = __ldg(&g_cbox[g]);
            ok = (cb.x <= ftx1) & (cb.y >= ftx0) &
                 (cb.z <= fty1) & (cb.w >= fty0);
        }
        unsigned m = __ballot_sync(0xffffffffu, ok);
        if (ok) myidx[cnt + __popc(m & ((1u << lane) - 1u))] = (unsigned short)g;
        cnt += __popc(m);
    }

    // ---- phase A: local strict running minima -> smem records ----
    const int entBase = warp * SLOTS * 32 + lane;
    float runmin = INF;
    float lastz  = INF;
    int mycnt = 0;
    for (int i0 = 0; i0 < cnt; i0 += 2) {
        int r = cnt - i0;
        int gg[2]; float4 P1[2], P2[2];
        #pragma unroll
        for (int k = 0; k < 2; k++) {
            int idx = (k < r) ? (int)myidx[i0 + k] : 0;
            gg[k] = idx & (MAX_N - 1);
            P1[k] = __ldg(&g_pk[gg[k] * 2 + 0]);
            P2[k] = __ldg(&g_pk[gg[k] * 2 + 1]);
        }
        #pragma unroll
        for (int k = 0; k < 2; k++) {
            float dx = px - P1[k].x;
            float dy = py - P1[k].y;
            float d2 = P1[k].z * dx * dx + P1[k].w * dx * dy + P2[k].x * dy * dy;
            unsigned pk = __float_as_uint(P2[k].w);
            bool inb = (px_i >= (int)(pk & 0xFF)) &
                       (px_i <= (int)((pk >> 8) & 0xFF)) &
                       (py_i >= (int)((pk >> 16) & 0xFF)) &
                       (py_i <= (int)(pk >> 24));
            bool acc = (k < r) & inb & (d2 < 9.0f) & (P2[k].z < runmin);
            float a  = P2[k].y * __expf(-0.5f * d2);  // speculative, MUFU
            if (acc) {
                runmin = P2[k].z;
                if (mycnt < SLOTS) {
                    s_rec[entBase + mycnt * 32] = make_float2(P2[k].z, a);
                    s_gid[entBase + mycnt * 32] = (unsigned short)gg[k];
                    lastz = P2[k].z;
                }
                mycnt++;
            }
        }
    }
    const int c = min(mycnt, SLOTS);
    s_lastz[warp * 32 + lane] = lastz;
    __syncthreads();

    // ---- phase B1: thr (prefix-min of lastz) + local transmittance Tseg ----
    float thr = INF;
    #pragma unroll
    for (int s = 0; s < SEGS - 1; s++) {
        float v = s_lastz[s * 32 + lane];
        thr = (s < warp) ? fminf(thr, v) : thr;
    }

    float Tseg = 1.0f;
    for (int j = 0; j < c; j++) {
        float2 rec = s_rec[entBase + j * 32];
        Tseg *= (rec.x < thr) ? (1.0f - rec.y) : 1.0f;
    }
    s_Tseg[warp * 32 + lane] = Tseg;
    __syncthreads();

    // ---- phase B2: T_in prefix product + affine fold (A, B), 2-wide MLP ----
    float T_in = 1.0f;
    #pragma unroll
    for (int s = 0; s < SEGS - 1; s++) {
        float v = s_Tseg[s * 32 + lane];
        T_in *= (s < warp) ? v : 1.0f;
    }

    float A = 1.0f, B0 = 0.0f, B1 = 0.0f, B2 = 0.0f;
    {
        float T = T_in;
        for (int j0 = 0; j0 < c; j0 += 2) {
            int r = c - j0;
            float2 rec[2]; float4 col[2];
            #pragma unroll
            for (int k = 0; k < 2; k++) {
                int e = entBase + min(j0 + k, SLOTS - 1) * 32;
                rec[k] = s_rec[e];
                int gid = (int)s_gid[e] & (MAX_N - 1);
                col[k] = __ldg(&g_col[gid]);
            }
            #pragma unroll
            for (int k = 0; k < 2; k++) {
                bool acc = (k < r) & (rec[k].x < thr);
                float na = acc ? rec[k].y * T : 0.0f;
                float om = 1.0f - na;
                A  = A  * om;
                B0 = B0 * om + col[k].x * na;
                B1 = B1 * om + col[k].y * na;
                B2 = B2 * om + col[k].z * na;
                T  = T - na;              // T' = T(1-a) = T - a*T
            }
        }
    }
    s_AB[warp * 32 + lane] = make_float4(A, B0, B1, B2);
    __syncthreads();

    // ---- phase B3: apply 16 affine maps in order (warp 0) ----
    if (warp == 0) {
        float i0v = 0.0f, i1v = 0.0f, i2v = 0.0f;
        #pragma unroll
        for (int s = 0; s < SEGS; s++) {
            float4 ab = s_AB[s * 32 + lane];
            i0v = ab.x * i0v + ab.y;
            i1v = ab.x * i1v + ab.z;
            i2v = ab.x * i2v + ab.w;
        }
        int o = (py_i * IMG_W + px_i) * 3;
        out[o + 0] = i0v;
        out[o + 1] = i1v;
        out[o + 2] = i2v;
    }
}

extern "C" void kernel_launch(void* const* d_in, const int* in_sizes, int n_in,
                              void* d_out, int out_size)
{
    const float* means  = (const float*)d_in[0];
    const float* scales = (const float*)d_in[1];
    const float* rots   = (const float*)d_in[2];
    const float* opac   = (const float*)d_in[3];
    const float* feats  = (const float*)d_in[4];
    const float* cam    = (const float*)d_in[5];
    const float* focal  = (const float*)d_in[6];
    const float* cx     = (const float*)d_in[7];
    const float* cy     = (const float*)d_in[8];
    float* out = (float*)d_out;

    int N = in_sizes[0] / 3;
    if (N > MAX_N) N = MAX_N;

    // 32-thread blocks spread the latency-bound per-gaussian math across SMs
    gs_precompute<<<(N + 31) / 32, 32>>>(means, scales, rots, opac, feats,
                                         cam, focal, cx, cy, N);

    int segLen = (N + SEGS - 1) / SEGS;
    size_t smem = (size_t)SEGS * SLOTS * 32 * sizeof(float2)          // records
                + (size_t)SEGS * 32 * sizeof(float4)                  // A,B
                + (size_t)SEGS * 32 * sizeof(float) * 2               // lastz,Tseg
                + (size_t)SEGS * SLOTS * 32 * sizeof(unsigned short)  // gids
                + (size_t)SEGS * segLen * sizeof(unsigned short);     // idx lists
    cudaFuncSetAttribute(gs_render, cudaFuncAttributeMaxDynamicSharedMemorySize,
                         56 * 1024);

    dim3 block(SEGS * 32, 1);
    gs_render<<<NTILES, block, smem>>>(out, N);
}

// round 15
// speedup vs baseline: 1.1528x; 1.0157x over previous
#include <cuda_runtime.h>
#include <math.h>

#define IMG_W 128
#define IMG_H 128
#define MAX_N 4096
#define TILE_W 8
#define TILE_H 4
#define SEGS   16
#define SLOTS  8
#define NTILES ((IMG_W / TILE_W) * (IMG_H / TILE_H))   // 512

// Packed hot params, 2 x float4 per gaussian:
//  [0] u, v, ia, ibc
//  [1] idd, lop(=ln op), z, bbox packed as uchar4 (minu, maxu, minv, maxv)
__device__ float4 g_pk[MAX_N * 2];
// Colors (phase B only).
__device__ float4 g_col[MAX_N];
// Byte-packed tightened cull box (conservative): (minu, maxu, minv, maxv).
__device__ unsigned g_cboxb[MAX_N];

__global__ __launch_bounds__(32)
void gs_precompute(const float* __restrict__ means,
                   const float* __restrict__ scales,
                   const float* __restrict__ rots,
                   const float* __restrict__ opac,
                   const float* __restrict__ feats,
                   const float* __restrict__ cam,
                   const float* __restrict__ focal_p,
                   const float* __restrict__ cx_p,
                   const float* __restrict__ cy_p,
                   int N)
{
    int g = blockIdx.x * blockDim.x + threadIdx.x;
    if (g >= N) return;

    const float f  = focal_p[0];
    const float cx = cx_p[0];
    const float cy = cy_p[0];

    float R[3][3], t[3];
    #pragma unroll
    for (int i = 0; i < 3; i++) {
        #pragma unroll
        for (int k = 0; k < 3; k++) R[i][k] = cam[i * 4 + k];
        t[i] = cam[i * 4 + 3];
    }

    float mean[3], sc[3];
    #pragma unroll
    for (int k = 0; k < 3; k++) {
        mean[k] = means[g * 3 + k];
        sc[k]   = __expf(scales[g * 3 + k]);
    }

    float qw = rots[g * 4 + 0], qx = rots[g * 4 + 1];
    float qy = rots[g * 4 + 2], qz = rots[g * 4 + 3];
    float two_s = __fdividef(2.0f, qw * qw + qx * qx + qy * qy + qz * qz);
    float xx = qx * qx * two_s, xy = qx * qy * two_s, xz = qx * qz * two_s;
    float yw = qy * qw * two_s, yy = qy * qy * two_s, yz = qy * qz * two_s;
    float zw = qz * qw * two_s, zz = qz * qz * two_s, xw = qx * qw * two_s;
    float M[3][3];
    M[0][0] = 1.0f - (yy + zz); M[0][1] = xy - zw;          M[0][2] = xz + yw;
    M[1][0] = xy + zw;          M[1][1] = 1.0f - (xx + zz); M[1][2] = yz - xw;
    M[2][0] = xz - yw;          M[2][1] = yz + xw;          M[2][2] = 1.0f - (xx + yy);

    float mc[3];
    #pragma unroll
    for (int i = 0; i < 3; i++)
        mc[i] = R[i][0] * mean[0] + R[i][1] * mean[1] + R[i][2] * mean[2] + t[i];
    float z = mc[2];
    float inv_z = __fdividef(1.0f, z);
    float u = mc[0] * inv_z * f + cx;
    float v = mc[1] * inv_z * f + cy;

    float J0[3], J1[3];
    #pragma unroll
    for (int k = 0; k < 3; k++) {
        J0[k] = f * R[0][k] - cx * R[2][k];
        J1[k] = f * R[1][k] - cy * R[2][k];
    }

    float V0[3], V1[3];
    #pragma unroll
    for (int k = 0; k < 3; k++) {
        V0[k] = (J0[0] * M[0][k] + J0[1] * M[1][k] + J0[2] * M[2][k]) * sc[k];
        V1[k] = (J1[0] * M[0][k] + J1[1] * M[1][k] + J1[2] * M[2][k]) * sc[k];
    }

    float inv_z2 = inv_z * inv_z;
    float a = (V0[0] * V0[0] + V0[1] * V0[1] + V0[2] * V0[2]) * inv_z2;
    float b = (V0[0] * V1[0] + V0[1] * V1[1] + V0[2] * V1[2]) * inv_z2;
    float d = (V1[0] * V1[0] + V1[1] * V1[1] + V1[2] * V1[2]) * inv_z2;
    float det = a * d - b * b;
    float invdet = __fdividef(1.0f, det);
    float ia  = d * invdet;
    float ibc = -(b + b) * invdet;
    float idd = a * invdet;

    // lop = ln(sigmoid(x)) = -ln(1 + exp(-x));  amplitude folded into exponent
    float lop = -__logf(1.0f + __expf(-opac[g]));
    float c0 = __fdividef(1.0f, 1.0f + __expf(-feats[g * 3 + 0]));
    float c1 = __fdividef(1.0f, 1.0f + __expf(-feats[g * 3 + 1]));
    float c2 = __fdividef(1.0f, 1.0f + __expf(-feats[g * 3 + 2]));

    float smax = fmaxf(sc[0], fmaxf(sc[1], sc[2]));
    float radius = smax * f * inv_z * 3.0f;

    float minu = fmaxf(0.0f, truncf(u - radius));
    float maxu = truncf(u + radius);
    float minv = fmaxf(0.0f, truncf(v - radius));
    float maxv = truncf(v + radius);

    // pack refbox as bytes; clamps preserve exact comparisons for px,py in 0..127
    unsigned pumin = (unsigned)fminf(minu, 255.0f);
    unsigned pumax = (unsigned)fminf(fmaxf(maxu, 0.0f), 255.0f);
    unsigned pvmin = (unsigned)fminf(minv, 255.0f);
    unsigned pvmax = (unsigned)fminf(fmaxf(maxv, 0.0f), 255.0f);
    unsigned pack = pumin | (pumax << 8) | (pvmin << 16) | (pvmax << 24);

    g_pk[g * 2 + 0] = make_float4(u, v, ia, ibc);
    g_pk[g * 2 + 1] = make_float4(idd, lop, z, __uint_as_float(pack));
    g_col[g] = make_float4(c0, c1, c2, 0.0f);

    // tightened cull box (refbox ∩ 3-sigma extents), byte-packed CONSERVATIVELY:
    // floor on mins (more inclusive for <= tests), ceil on maxes.
    float cbx = fmaxf(minu, u - 3.0f * sqrtf(fmaxf(a, 0.0f)));
    float cby = fminf(maxu, u + 3.0f * sqrtf(fmaxf(a, 0.0f)));
    float cbz = fmaxf(minv, v - 3.0f * sqrtf(fmaxf(d, 0.0f)));
    float cbw = fminf(maxv, v + 3.0f * sqrtf(fmaxf(d, 0.0f)));
    unsigned cminu = (unsigned)fminf(fmaxf(floorf(cbx), 0.0f), 255.0f);
    unsigned cmaxu = (unsigned)fminf(fmaxf(ceilf (cby), 0.0f), 255.0f);
    unsigned cminv = (unsigned)fminf(fmaxf(floorf(cbz), 0.0f), 255.0f);
    unsigned cmaxv = (unsigned)fminf(fmaxf(ceilf (cbw), 0.0f), 255.0f);
    g_cboxb[g] = cminu | (cmaxu << 8) | (cminv << 16) | (cmaxv << 24);
}

// 16 warps / 8x4 tile, 3 blocks/SM. Phase A: per-warp segment cull (SIMD
// byte compares) + local strict-running-min records. Phase B: thr =
// prefix-min of earlier segments' lastz; record accepted iff z < thr
// (suffix property). Per-warp Tseg -> prefix product -> T_in -> per-warp
// affine fold (A,B); warp 0 applies the 16 affine maps in order.
__global__ __launch_bounds__(SEGS * 32, 3)
void gs_render(float* __restrict__ out, int N)
{
    extern __shared__ char smem_raw[];
    float2*         s_rec   = (float2*)smem_raw;                    // 32 KB
    float4*         s_AB    = (float4*)(s_rec + SEGS * SLOTS * 32); //  8 KB
    float*          s_lastz = (float*)(s_AB + SEGS * 32);           //  2 KB
    float*          s_Tseg  = s_lastz + SEGS * 32;                  //  2 KB
    unsigned short* s_gid   = (unsigned short*)(s_Tseg + SEGS * 32);//  8 KB
    unsigned short* s_idx   = s_gid + SEGS * SLOTS * 32;            //  2 KB

    const int warp = threadIdx.x >> 5;
    const int lane = threadIdx.x & 31;

    const int segLen = (N + SEGS - 1) / SEGS;
    const int segBeg = warp * segLen;
    const int segEnd = min(segBeg + segLen, N);
    const float INF = __int_as_float(0x7f800000);

    const int tile = blockIdx.x;
    const int tx0 = (tile & 15) * TILE_W;
    const int ty0 = (tile >> 4) * TILE_H;
    const int px_i = tx0 + (lane & (TILE_W - 1));
    const int py_i = ty0 + (lane >> 3);
    const float px = (float)px_i;
    const float py = (float)py_i;

    // byte packs for SIMD compares
    const unsigned pp = (unsigned)px_i | ((unsigned)px_i << 8) |
                        ((unsigned)py_i << 16) | ((unsigned)py_i << 24);
    const unsigned tt = (unsigned)(tx0 + TILE_W - 1) | ((unsigned)tx0 << 8) |
                        ((unsigned)(ty0 + TILE_H - 1) << 16) | ((unsigned)ty0 << 24);

    // ---- cull segment: SIMD byte compare against byte cull box ----
    unsigned short* myidx = s_idx + warp * segLen;
    int cnt = 0;
    for (int j = segBeg; j < segEnd; j += 32) {
        int g = j + lane;
        bool ok = false;
        if (g < segEnd) {
            unsigned cb = __ldg(&g_cboxb[g]);
            // test: tx1>=minu & maxu>=tx0 & ty1>=minv & maxv>=ty0
            unsigned X = __byte_perm(cb, tt, 0x3614);
            unsigned Y = __byte_perm(cb, tt, 0x7250);
            ok = (__vcmpgeu4(X, Y) == 0xFFFFFFFFu);
        }
        unsigned m = __ballot_sync(0xffffffffu, ok);
        if (ok) myidx[cnt + __popc(m & ((1u << lane) - 1u))] = (unsigned short)g;
        cnt += __popc(m);
    }

    // ---- phase A: local strict running minima -> smem records ----
    const int entBase = warp * SLOTS * 32 + lane;
    float runmin = INF;
    float lastz  = INF;
    int mycnt = 0;
    for (int i0 = 0; i0 < cnt; i0 += 2) {
        int r = cnt - i0;
        int gg[2]; float4 P1[2], P2[2];
        #pragma unroll
        for (int k = 0; k < 2; k++) {
            int idx = (k < r) ? (int)myidx[i0 + k] : 0;
            gg[k] = idx & (MAX_N - 1);
            P1[k] = __ldg(&g_pk[gg[k] * 2 + 0]);
            P2[k] = __ldg(&g_pk[gg[k] * 2 + 1]);
        }
        #pragma unroll
        for (int k = 0; k < 2; k++) {
            float dx = px - P1[k].x;
            float dy = py - P1[k].y;
            float d2 = P1[k].z * dx * dx + P1[k].w * dx * dy + P2[k].x * dy * dy;
            unsigned pk = __float_as_uint(P2[k].w);
            // test: px>=minu & maxu>=px & py>=minv & maxv>=py
            unsigned X = __byte_perm(pk, pp, 0x3614);
            unsigned Y = __byte_perm(pk, pp, 0x7250);
            bool inb = (__vcmpgeu4(X, Y) == 0xFFFFFFFFu);
            bool acc = (k < r) & inb & (d2 < 9.0f) & (P2[k].z < runmin);
            float a  = __expf(fmaf(-0.5f, d2, P2[k].y));  // op folded into exp
            if (acc) {
                runmin = P2[k].z;
                if (mycnt < SLOTS) {
                    s_rec[entBase + mycnt * 32] = make_float2(P2[k].z, a);
                    s_gid[entBase + mycnt * 32] = (unsigned short)gg[k];
                    lastz = P2[k].z;
                }
                mycnt++;
            }
        }
    }
    const int c = min(mycnt, SLOTS);
    s_lastz[warp * 32 + lane] = lastz;
    __syncthreads();

    // ---- phase B1: thr (prefix-min of lastz) + local transmittance Tseg ----
    float thr = INF;
    #pragma unroll
    for (int s = 0; s < SEGS - 1; s++) {
        float v = s_lastz[s * 32 + lane];
        thr = (s < warp) ? fminf(thr, v) : thr;
    }

    float Tseg = 1.0f;
    for (int j = 0; j < c; j++) {
        float2 rec = s_rec[entBase + j * 32];
        Tseg *= (rec.x < thr) ? (1.0f - rec.y) : 1.0f;
    }
    s_Tseg[warp * 32 + lane] = Tseg;
    __syncthreads();

    // ---- phase B2: T_in prefix product + affine fold (A, B), 2-wide MLP ----
    float T_in = 1.0f;
    #pragma unroll
    for (int s = 0; s < SEGS - 1; s++) {
        float v = s_Tseg[s * 32 + lane];
        T_in *= (s < warp) ? v : 1.0f;
    }

    float A = 1.0f, B0 = 0.0f, B1 = 0.0f, B2 = 0.0f;
    {
        float T = T_in;
        for (int j0 = 0; j0 < c; j0 += 2) {
            int r = c - j0;
            float2 rec[2]; float4 col[2];
            #pragma unroll
            for (int k = 0; k < 2; k++) {
                int e = entBase + min(j0 + k, SLOTS - 1) * 32;
                rec[k] = s_rec[e];
                int gid = (int)s_gid[e] & (MAX_N - 1);
                col[k] = __ldg(&g_col[gid]);
            }
            #pragma unroll
            for (int k = 0; k < 2; k++) {
                bool acc = (k < r) & (rec[k].x < thr);
                float na = acc ? rec[k].y * T : 0.0f;
                float om = 1.0f - na;
                A  = A  * om;
                B0 = B0 * om + col[k].x * na;
                B1 = B1 * om + col[k].y * na;
                B2 = B2 * om + col[k].z * na;
                T  = T - na;              // T' = T(1-a) = T - a*T
            }
        }
    }
    s_AB[warp * 32 + lane] = make_float4(A, B0, B1, B2);
    __syncthreads();

    // ---- phase B3: apply 16 affine maps in order (warp 0) ----
    if (warp == 0) {
        float i0v = 0.0f, i1v = 0.0f, i2v = 0.0f;
        #pragma unroll
        for (int s = 0; s < SEGS; s++) {
            float4 ab = s_AB[s * 32 + lane];
            i0v = ab.x * i0v + ab.y;
            i1v = ab.x * i1v + ab.z;
            i2v = ab.x * i2v + ab.w;
        }
        int o = (py_i * IMG_W + px_i) * 3;
        out[o + 0] = i0v;
        out[o + 1] = i1v;
        out[o + 2] = i2v;
    }
}

extern "C" void kernel_launch(void* const* d_in, const int* in_sizes, int n_in,
                              void* d_out, int out_size)
{
    const float* means  = (const float*)d_in[0];
    const float* scales = (const float*)d_in[1];
    const float* rots   = (const float*)d_in[2];
    const float* opac   = (const float*)d_in[3];
    const float* feats  = (const float*)d_in[4];
    const float* cam    = (const float*)d_in[5];
    const float* focal  = (const float*)d_in[6];
    const float* cx     = (const float*)d_in[7];
    const float* cy     = (const float*)d_in[8];
    float* out = (float*)d_out;

    int N = in_sizes[0] / 3;
    if (N > MAX_N) N = MAX_N;

    // 32-thread blocks spread the latency-bound per-gaussian math across SMs
    gs_precompute<<<(N + 31) / 32, 32>>>(means, scales, rots, opac, feats,
                                         cam, focal, cx, cy, N);

    int segLen = (N + SEGS - 1) / SEGS;
    size_t smem = (size_t)SEGS * SLOTS * 32 * sizeof(float2)          // records
                + (size_t)SEGS * 32 * sizeof(float4)                  // A,B
                + (size_t)SEGS * 32 * sizeof(float) * 2               // lastz,Tseg
                + (size_t)SEGS * SLOTS * 32 * sizeof(unsigned short)  // gids
                + (size_t)SEGS * segLen * sizeof(unsigned short);     // idx lists
    cudaFuncSetAttribute(gs_render, cudaFuncAttributeMaxDynamicSharedMemorySize,
                         56 * 1024);

    dim3 block(SEGS * 32, 1);
    gs_render<<<NTILES, block, smem>>>(out, N);
}